// round 2
// baseline (speedup 1.0000x reference)
#include <cuda_runtime.h>
#include <cuda_bf16.h>
#include <math.h>

// Problem constants
#define NE    65536      // edges
#define NL    3          // metapath length
#define NELT  196608     // NE*NL tokens
#define NN    20000      // nodes
#define NT    16384      // targets
#define ND    128        // model dim
#define NFF   2048       // FF dim
#define NAH   4          // attention heads
#define NHD   32         // head dim
#define NH    8          // output heads
#define CH    49152      // FFN M-chunk (NELT/4)

// ---------------------------------------------------------------------------
// Static device scratch (cudaMalloc is banned; __device__ globals are the
// sanctioned workaround). ~1.5 GB total.
// ---------------------------------------------------------------------------
__device__ float    g_x     [(size_t)NELT * ND];        // gathered features (residual 1)
__device__ float    g_qkv   [(size_t)NELT * 3 * ND];    // qkv projection
__device__ float    g_attn  [(size_t)NELT * ND];        // attention output
__device__ float    g_x1    [(size_t)NELT * ND];        // post-LN1
__device__ float    g_h     [(size_t)CH   * NFF];       // FFN hidden (chunked)
__device__ float    g_ffo   [(size_t)NELT * ND];        // out-proj out, then FFN out
__device__ float    g_hidden[(size_t)NE   * ND];        // mean over L
__device__ float    g_eft   [(size_t)NE   * NH * ND];   // rnn projection
__device__ float    g_a     [(size_t)NE   * NH];
__device__ float    g_expa  [(size_t)NE   * NH];
__device__ unsigned g_menc  [(size_t)NN   * NH];        // encoded segment max
__device__ float    g_s     [(size_t)NN   * NH];        // segment sum
__device__ float    g_ft    [(size_t)NN   * NH * ND];   // segment weighted sum

// ---------------------------------------------------------------------------
// f32x2 packed-FMA helpers (Blackwell sm_100+): 2 fp32 FMAs per instruction.
// Scalar 3-reg FFMA is half-rate on this chip; packed restores full rate.
// ---------------------------------------------------------------------------
__device__ __forceinline__ unsigned long long pk2(float x, float y) {
    unsigned long long r;
    asm("mov.b64 %0, {%1, %2};" : "=l"(r) : "f"(x), "f"(y));
    return r;
}
__device__ __forceinline__ float2 upk2(unsigned long long v) {
    float2 r;
    asm("mov.b64 {%0, %1}, %2;" : "=f"(r.x), "=f"(r.y) : "l"(v));
    return r;
}
__device__ __forceinline__ void fma2(unsigned long long& d,
                                     unsigned long long a,
                                     unsigned long long b) {
    asm("fma.rn.f32x2 %0, %1, %2, %0;" : "+l"(d) : "l"(a), "l"(b));
}

// Ordered-uint encoding of float for atomicMax (handles negatives).
__device__ __forceinline__ unsigned encf(float f) {
    unsigned u = __float_as_uint(f);
    return (u & 0x80000000u) ? ~u : (u | 0x80000000u);
}
__device__ __forceinline__ float decf(unsigned u) {
    return (u & 0x80000000u) ? __uint_as_float(u ^ 0x80000000u)
                             : __uint_as_float(~u);
}

// ---------------------------------------------------------------------------
// K0: zero per-launch accumulators (graph replay -> must reset every call)
// ---------------------------------------------------------------------------
__global__ void zero_kernel() {
    int i = blockIdx.x * 256 + threadIdx.x;
    if (i < NN * NH * ND) g_ft[i] = 0.0f;
    if (i < NN * NH) { g_s[i] = 0.0f; g_menc[i] = 0u; }
}

// ---------------------------------------------------------------------------
// K1: gather node features for every token (float4 per thread)
// ---------------------------------------------------------------------------
__global__ void gather_kernel(const float* __restrict__ feat,
                              const int* __restrict__ emi) {
    int i = blockIdx.x * 256 + threadIdx.x;          // NELT*32 threads exactly
    int r = i >> 5;
    int c = (i & 31) << 2;
    int node = emi[r];
    *(float4*)&g_x[(size_t)r * ND + c] =
        *(const float4*)&feat[(size_t)node * ND + c];
}

// ---------------------------------------------------------------------------
// Generic SGEMM: C[M,N] = act(A[M,K] @ W[N,K]^T + bias)
// BM=64, BN=128, BK=16, 256 threads, 4x8 micro-tile with f32x2 packed FMA.
// All launch shapes are exact tile multiples -> no bounds checks.
// ---------------------------------------------------------------------------
#define BM 64
#define BN 128
#define BK 16

__global__ __launch_bounds__(256)
void sgemm_kernel(const float* __restrict__ A, const float* __restrict__ W,
                  const float* __restrict__ bias, float* __restrict__ C,
                  int N, int K, int relu) {
    __shared__ float As[BK][BM + 4];
    __shared__ float Ws[BK][BN + 4];

    const int tid = threadIdx.x;
    const int tx = tid & 15;          // 16 col groups * 8 cols
    const int ty = tid >> 4;          // 16 row groups * 4 rows
    const size_t bm = (size_t)blockIdx.x * BM;
    const size_t bn = (size_t)blockIdx.y * BN;

    const int lrow = tid >> 2;        // 0..63
    const int lk   = (tid & 3) << 2;  // 0,4,8,12
    const float* Ap  = A + (bm + lrow) * (size_t)K + lk;
    const float* Wp0 = W + (bn + lrow) * (size_t)K + lk;
    const float* Wp1 = W + (bn + lrow + 64) * (size_t)K + lk;

    unsigned long long acc[4][4];
#pragma unroll
    for (int i = 0; i < 4; i++)
#pragma unroll
        for (int j = 0; j < 4; j++) acc[i][j] = 0ull;

    for (int k0 = 0; k0 < K; k0 += BK) {
        float4 a4 = *(const float4*)(Ap + k0);
        float4 w0 = *(const float4*)(Wp0 + k0);
        float4 w1 = *(const float4*)(Wp1 + k0);
        As[lk + 0][lrow] = a4.x; As[lk + 1][lrow] = a4.y;
        As[lk + 2][lrow] = a4.z; As[lk + 3][lrow] = a4.w;
        Ws[lk + 0][lrow] = w0.x; Ws[lk + 1][lrow] = w0.y;
        Ws[lk + 2][lrow] = w0.z; Ws[lk + 3][lrow] = w0.w;
        Ws[lk + 0][lrow + 64] = w1.x; Ws[lk + 1][lrow + 64] = w1.y;
        Ws[lk + 2][lrow + 64] = w1.z; Ws[lk + 3][lrow + 64] = w1.w;
        __syncthreads();
#pragma unroll
        for (int kk = 0; kk < BK; kk++) {
            float4 av = *(const float4*)&As[kk][ty * 4];
            float4 b0 = *(const float4*)&Ws[kk][tx * 8];
            float4 b1 = *(const float4*)&Ws[kk][tx * 8 + 4];
            unsigned long long bp0 = pk2(b0.x, b0.y), bp1 = pk2(b0.z, b0.w);
            unsigned long long bp2 = pk2(b1.x, b1.y), bp3 = pk2(b1.z, b1.w);
            unsigned long long a0 = pk2(av.x, av.x), a1 = pk2(av.y, av.y);
            unsigned long long a2 = pk2(av.z, av.z), a3 = pk2(av.w, av.w);
            fma2(acc[0][0], a0, bp0); fma2(acc[0][1], a0, bp1);
            fma2(acc[0][2], a0, bp2); fma2(acc[0][3], a0, bp3);
            fma2(acc[1][0], a1, bp0); fma2(acc[1][1], a1, bp1);
            fma2(acc[1][2], a1, bp2); fma2(acc[1][3], a1, bp3);
            fma2(acc[2][0], a2, bp0); fma2(acc[2][1], a2, bp1);
            fma2(acc[2][2], a2, bp2); fma2(acc[2][3], a2, bp3);
            fma2(acc[3][0], a3, bp0); fma2(acc[3][1], a3, bp1);
            fma2(acc[3][2], a3, bp2); fma2(acc[3][3], a3, bp3);
        }
        __syncthreads();
    }

    const int colbase = tx * 8;
    float bi[8];
#pragma unroll
    for (int j = 0; j < 8; j++) bi[j] = bias[bn + colbase + j];

#pragma unroll
    for (int i = 0; i < 4; i++) {
        size_t row = bm + ty * 4 + i;
        float* Crow = C + row * (size_t)N + bn + colbase;
#pragma unroll
        for (int j = 0; j < 4; j++) {
            float2 v = upk2(acc[i][j]);
            float r0 = v.x + bi[j * 2];
            float r1 = v.y + bi[j * 2 + 1];
            if (relu) { r0 = fmaxf(r0, 0.0f); r1 = fmaxf(r1, 0.0f); }
            Crow[j * 2]     = r0;
            Crow[j * 2 + 1] = r1;
        }
    }
}

// ---------------------------------------------------------------------------
// K3: tiny attention (L=3, AH=4, HD=32) — one warp per edge, lane = head dim
// ---------------------------------------------------------------------------
__global__ __launch_bounds__(256)
void attn_kernel() {
    int warp = (blockIdx.x * blockDim.x + threadIdx.x) >> 5;
    int lane = threadIdx.x & 31;
    const float* base = g_qkv + (size_t)warp * NL * 3 * ND;

    float q[NL][NAH], k[NL][NAH], v[NL][NAH];
#pragma unroll
    for (int l = 0; l < NL; l++)
#pragma unroll
        for (int h = 0; h < NAH; h++) {
            q[l][h] = base[l * 384 + h * 32 + lane];
            k[l][h] = base[l * 384 + 128 + h * 32 + lane];
            v[l][h] = base[l * 384 + 256 + h * 32 + lane];
        }

    const float scale = 0.1767766952966369f; // 1/sqrt(32)
    float o[NL][NAH];
#pragma unroll
    for (int h = 0; h < NAH; h++) {
#pragma unroll
        for (int l = 0; l < NL; l++) {
            float s[NL];
#pragma unroll
            for (int m = 0; m < NL; m++) {
                float p = q[l][h] * k[m][h];
#pragma unroll
                for (int off = 16; off; off >>= 1)
                    p += __shfl_xor_sync(0xFFFFFFFFu, p, off);
                s[m] = p * scale;
            }
            float mx = fmaxf(s[0], fmaxf(s[1], s[2]));
            float e0 = expf(s[0] - mx), e1 = expf(s[1] - mx), e2 = expf(s[2] - mx);
            float inv = 1.0f / (e0 + e1 + e2);
            o[l][h] = (e0 * v[0][h] + e1 * v[1][h] + e2 * v[2][h]) * inv;
        }
    }
#pragma unroll
    for (int l = 0; l < NL; l++)
#pragma unroll
        for (int h = 0; h < NAH; h++)
            g_attn[((size_t)warp * NL + l) * ND + h * 32 + lane] = o[l][h];
}

// ---------------------------------------------------------------------------
// K5: out = LN(X + Y) — one warp per row of 128
// ---------------------------------------------------------------------------
__global__ __launch_bounds__(256)
void addln_kernel(const float* __restrict__ X, const float* __restrict__ Y,
                  const float* __restrict__ gam, const float* __restrict__ bet,
                  float* __restrict__ out) {
    int warp = (blockIdx.x * blockDim.x + threadIdx.x) >> 5;
    int lane = threadIdx.x & 31;
    const float* xr = X + (size_t)warp * ND;
    const float* yr = Y + (size_t)warp * ND;
    float v[4], s = 0.0f;
#pragma unroll
    for (int i = 0; i < 4; i++) {
        v[i] = xr[i * 32 + lane] + yr[i * 32 + lane];
        s += v[i];
    }
#pragma unroll
    for (int off = 16; off; off >>= 1) s += __shfl_xor_sync(0xFFFFFFFFu, s, off);
    float mu = s * (1.0f / 128.0f);
    float vs = 0.0f;
#pragma unroll
    for (int i = 0; i < 4; i++) { float d = v[i] - mu; vs += d * d; }
#pragma unroll
    for (int off = 16; off; off >>= 1) vs += __shfl_xor_sync(0xFFFFFFFFu, vs, off);
    float inv = rsqrtf(vs * (1.0f / 128.0f) + 1e-5f);
    float* orow = out + (size_t)warp * ND;
#pragma unroll
    for (int i = 0; i < 4; i++)
        orow[i * 32 + lane] =
            (v[i] - mu) * inv * gam[i * 32 + lane] + bet[i * 32 + lane];
}

// ---------------------------------------------------------------------------
// K7: LN2 + mean over L -> hidden. One warp per edge (3 rows).
// ---------------------------------------------------------------------------
__global__ __launch_bounds__(256)
void ln2hidden_kernel(const float* __restrict__ gam, const float* __restrict__ bet) {
    int warp = (blockIdx.x * blockDim.x + threadIdx.x) >> 5;
    int lane = threadIdx.x & 31;
    float hid[4] = {0, 0, 0, 0};
#pragma unroll
    for (int l = 0; l < NL; l++) {
        size_t r = (size_t)warp * NL + l;
        const float* xr = g_x1 + r * ND;
        const float* yr = g_ffo + r * ND;
        float v[4], s = 0.0f;
#pragma unroll
        for (int i = 0; i < 4; i++) {
            v[i] = xr[i * 32 + lane] + yr[i * 32 + lane];
            s += v[i];
        }
#pragma unroll
        for (int off = 16; off; off >>= 1) s += __shfl_xor_sync(0xFFFFFFFFu, s, off);
        float mu = s * (1.0f / 128.0f);
        float vs = 0.0f;
#pragma unroll
        for (int i = 0; i < 4; i++) { float d = v[i] - mu; vs += d * d; }
#pragma unroll
        for (int off = 16; off; off >>= 1) vs += __shfl_xor_sync(0xFFFFFFFFu, vs, off);
        float inv = rsqrtf(vs * (1.0f / 128.0f) + 1e-5f);
#pragma unroll
        for (int i = 0; i < 4; i++)
            hid[i] += ((v[i] - mu) * inv * gam[i * 32 + lane] + bet[i * 32 + lane])
                      * (1.0f / 3.0f);
    }
#pragma unroll
    for (int i = 0; i < 4; i++)
        g_hidden[(size_t)warp * ND + i * 32 + lane] = hid[i];
}

// ---------------------------------------------------------------------------
// K9: per-edge attention logit + leaky relu + segment atomicMax
// ---------------------------------------------------------------------------
__global__ __launch_bounds__(256)
void amax_kernel(const float* __restrict__ feat, const int* __restrict__ emi,
                 const int* __restrict__ dst, const float* __restrict__ a1w,
                 const float* __restrict__ a2) {
    int warp = (blockIdx.x * blockDim.x + threadIdx.x) >> 5;
    int lane = threadIdx.x & 31;
    int node = emi[warp * NL + (NL - 1)];
    int d = dst[warp];
    float c[4];
#pragma unroll
    for (int i = 0; i < 4; i++) c[i] = feat[(size_t)node * ND + i * 32 + lane];
#pragma unroll
    for (int h = 0; h < NH; h++) {
        const float* w   = a1w + h * ND;
        const float* efr = g_eft + (size_t)warp * (NH * ND) + h * ND;
        const float* at2 = a2 + h * ND;
        float p = 0.0f;
#pragma unroll
        for (int i = 0; i < 4; i++)
            p += c[i] * w[i * 32 + lane] + efr[i * 32 + lane] * at2[i * 32 + lane];
#pragma unroll
        for (int off = 16; off; off >>= 1) p += __shfl_xor_sync(0xFFFFFFFFu, p, off);
        if (lane == 0) {
            float av = p > 0.0f ? p : 0.01f * p;
            g_a[warp * NH + h] = av;
            atomicMax(&g_menc[d * NH + h], encf(av));
        }
    }
}

// ---------------------------------------------------------------------------
// K10: e = exp(a - m[dst]); segment atomicAdd of e
// ---------------------------------------------------------------------------
__global__ void exps_kernel(const int* __restrict__ dst) {
    int i = blockIdx.x * 256 + threadIdx.x;
    int e = i >> 3, h = i & 7;
    int d = dst[e];
    float m = decf(g_menc[d * NH + h]);
    float ex = expf(g_a[i] - m);
    g_expa[i] = ex;
    atomicAdd(&g_s[d * NH + h], ex);
}

// ---------------------------------------------------------------------------
// K11: ft[dst] += eft * (e / s[dst])
// ---------------------------------------------------------------------------
__global__ void ftacc_kernel(const int* __restrict__ dst) {
    size_t i = (size_t)blockIdx.x * 256 + threadIdx.x;
    int e = (int)(i >> 10);
    int j = (int)(i & 1023);
    int h = j >> 7;
    int d = dst[e];
    float w = g_expa[e * NH + h] / g_s[d * NH + h];
    atomicAdd(&g_ft[(size_t)d * (NH * ND) + j], g_eft[i] * w);
}

// ---------------------------------------------------------------------------
// K12: out = ft[target_idx]
// ---------------------------------------------------------------------------
__global__ void outg_kernel(const int* __restrict__ tgt, float* __restrict__ out) {
    size_t i = (size_t)blockIdx.x * 256 + threadIdx.x;
    int t = (int)(i >> 10);
    int j = (int)(i & 1023);
    out[i] = g_ft[(size_t)tgt[t] * (NH * ND) + j];
}

// ---------------------------------------------------------------------------
extern "C" void kernel_launch(void* const* d_in, const int* in_sizes, int n_in,
                              void* d_out, int out_size) {
    const float* features = (const float*)d_in[0];
    const int*   emi      = (const int*)d_in[1];
    const int*   dst      = (const int*)d_in[2];
    const int*   tgt      = (const int*)d_in[3];
    const float* in_w     = (const float*)d_in[4];
    const float* in_b     = (const float*)d_in[5];
    const float* out_w    = (const float*)d_in[6];
    const float* out_b    = (const float*)d_in[7];
    const float* ln1_g    = (const float*)d_in[8];
    const float* ln1_b    = (const float*)d_in[9];
    const float* w1       = (const float*)d_in[10];
    const float* b1       = (const float*)d_in[11];
    const float* w2       = (const float*)d_in[12];
    const float* b2       = (const float*)d_in[13];
    const float* ln2_g    = (const float*)d_in[14];
    const float* ln2_b    = (const float*)d_in[15];
    const float* rnn_w    = (const float*)d_in[16];
    const float* rnn_b    = (const float*)d_in[17];
    const float* a1w      = (const float*)d_in[18];
    const float* a2       = (const float*)d_in[19];
    float* out = (float*)d_out;

    // Resolve device-global addresses (query-only; graph-capture safe)
    float *px, *pqkv, *pattn, *px1, *ph, *pffo, *phidden, *peft;
    cudaGetSymbolAddress((void**)&px,      g_x);
    cudaGetSymbolAddress((void**)&pqkv,    g_qkv);
    cudaGetSymbolAddress((void**)&pattn,   g_attn);
    cudaGetSymbolAddress((void**)&px1,     g_x1);
    cudaGetSymbolAddress((void**)&ph,      g_h);
    cudaGetSymbolAddress((void**)&pffo,    g_ffo);
    cudaGetSymbolAddress((void**)&phidden, g_hidden);
    cudaGetSymbolAddress((void**)&peft,    g_eft);

    // K0: zero accumulators (ft dominates: NN*1024 elements)
    zero_kernel<<<(NN * NH * ND + 255) / 256, 256>>>();

    // K1: gather features -> g_x   (NELT*32 threads, exact)
    gather_kernel<<<NELT * 32 / 256, 256>>>(features, emi);

    // K2: QKV projection: [NELT,128] @ [384,128]^T
    sgemm_kernel<<<dim3(NELT / BM, 384 / BN), 256>>>(
        px, in_w, in_b, pqkv, 384, ND, 0);

    // K3: attention (8 warps/block, NE warps total)
    attn_kernel<<<NE / 8, 256>>>();

    // K4: out projection -> g_ffo (temp)
    sgemm_kernel<<<dim3(NELT / BM, 1), 256>>>(
        pattn, out_w, out_b, pffo, ND, ND, 0);

    // K5: x1 = LN1(x + oproj)
    addln_kernel<<<NELT / 8, 256>>>(px, pffo, ln1_g, ln1_b, px1);

    // K6: FFN in 4 M-chunks (hidden scratch is CH x 2048)
    for (int c = 0; c < NELT / CH; c++) {
        const float* Ain = px1 + (size_t)c * CH * ND;
        float* Cout = pffo + (size_t)c * CH * ND;
        sgemm_kernel<<<dim3(CH / BM, NFF / BN), 256>>>(
            Ain, w1, b1, ph, NFF, ND, 1);
        sgemm_kernel<<<dim3(CH / BM, 1), 256>>>(
            ph, w2, b2, Cout, ND, NFF, 0);
    }

    // K7: x2 = LN2(x1 + ff), hidden = mean_L(x2)
    ln2hidden_kernel<<<NE / 8, 256>>>(ln2_g, ln2_b);

    // K8: eft = hidden @ rnn_w^T + rnn_b : [NE,128] @ [1024,128]^T
    sgemm_kernel<<<dim3(NE / BM, (NH * ND) / BN), 256>>>(
        phidden, rnn_w, rnn_b, peft, NH * ND, ND, 0);

    // K9: per-edge logits + leaky relu + segment max
    amax_kernel<<<NE / 8, 256>>>(features, emi, dst, a1w, a2);

    // K10: exp + segment sum  (NE*NH = 524288, exact multiple of 256)
    exps_kernel<<<NE * NH / 256, 256>>>(dst);

    // K11: weighted segment scatter (NE*NH*ND = 67.1M, exact multiple of 256)
    ftacc_kernel<<<(int)((size_t)NE * NH * ND / 256), 256>>>(dst);

    // K12: gather targets to output (NT*NH*ND = 16.8M, exact multiple of 256)
    outg_kernel<<<(int)((size_t)NT * NH * ND / 256), 256>>>(tgt, out);
}

// round 5
// speedup vs baseline: 2.1623x; 2.1623x over previous
#include <cuda_runtime.h>
#include <cuda_bf16.h>
#include <cstdint>
#include <math.h>

// Problem constants
#define NE    65536      // edges
#define NL    3          // metapath length
#define NELT  196608     // NE*NL tokens
#define NN    20000      // nodes
#define NT    16384      // targets
#define ND    128        // model dim
#define NFF   2048       // FF dim
#define NAH   4          // attention heads
#define NH    8          // output heads
#define CH    49152      // FFN M-chunk (NELT/4) -> keeps statics < 2GB for linker

typedef __nv_bfloat16 bf16;

// ---------------------------------------------------------------------------
// Static device scratch (~1.70 GB total; must stay < 2 GB or host link fails
// with GOTPCREL relocation overflow — learned in R4)
// ---------------------------------------------------------------------------
__device__ float g_x     [(size_t)NELT * ND];        // gathered features fp32
__device__ bf16  g_xh    [(size_t)NELT * ND];        // split planes of x
__device__ bf16  g_xl    [(size_t)NELT * ND];
__device__ float g_qkv   [(size_t)NELT * 3 * ND];    // qkv projection fp32
__device__ bf16  g_ah    [(size_t)NELT * ND];        // attention out planes
__device__ bf16  g_al    [(size_t)NELT * ND];
__device__ float g_x1    [(size_t)NELT * ND];        // post-LN1 fp32
__device__ bf16  g_x1h   [(size_t)NELT * ND];
__device__ bf16  g_x1l   [(size_t)NELT * ND];
__device__ bf16  g_hh    [(size_t)CH * NFF];         // FFN hidden planes (chunked)
__device__ bf16  g_hl    [(size_t)CH * NFF];
__device__ float g_ffo   [(size_t)NELT * ND];        // outproj out, then FFN out
__device__ bf16  g_hidh  [(size_t)NE * ND];          // hidden (mean over L)
__device__ bf16  g_hidl  [(size_t)NE * ND];
__device__ float g_eft   [(size_t)NE * NH * ND];     // rnn projection fp32
__device__ float g_a     [(size_t)NE * NH];
__device__ float g_expa  [(size_t)NE * NH];
__device__ unsigned g_menc[(size_t)NN * NH];
__device__ float g_s     [(size_t)NN * NH];
__device__ float g_ft    [(size_t)NN * NH * ND];
// weight planes
__device__ bf16 g_iwh[3 * ND * ND], g_iwl[3 * ND * ND];
__device__ bf16 g_owh[ND * ND],     g_owl[ND * ND];
__device__ bf16 g_w1h[NFF * ND],    g_w1l[NFF * ND];
__device__ bf16 g_w2h[ND * NFF],    g_w2l[ND * NFF];
__device__ bf16 g_rwh[NH * ND * ND],g_rwl[NH * ND * ND];

// ---------------------------------------------------------------------------
// Helpers
// ---------------------------------------------------------------------------
__device__ __forceinline__ uint32_t smem_u32(const void* p) {
    uint32_t a;
    asm("{ .reg .u64 t; cvta.to.shared.u64 t, %1; cvt.u32.u64 %0, t; }" : "=r"(a) : "l"(p));
    return a;
}
__device__ __forceinline__ void ldsm4(uint32_t* r, uint32_t addr) {
    asm volatile("ldmatrix.sync.aligned.m8n8.x4.shared.b16 {%0,%1,%2,%3}, [%4];"
                 : "=r"(r[0]), "=r"(r[1]), "=r"(r[2]), "=r"(r[3]) : "r"(addr));
}
__device__ __forceinline__ void mma16816(float* c, const uint32_t* a,
                                         uint32_t b0, uint32_t b1) {
    asm volatile("mma.sync.aligned.m16n8k16.row.col.f32.bf16.bf16.f32 "
                 "{%0,%1,%2,%3}, {%4,%5,%6,%7}, {%8,%9}, {%0,%1,%2,%3};"
                 : "+f"(c[0]), "+f"(c[1]), "+f"(c[2]), "+f"(c[3])
                 : "r"(a[0]), "r"(a[1]), "r"(a[2]), "r"(a[3]), "r"(b0), "r"(b1));
}
__device__ __forceinline__ void splitf(float v, bf16& h, bf16& l) {
    h = __float2bfloat16(v);
    l = __float2bfloat16(v - __bfloat162float(h));
}
__device__ __forceinline__ unsigned encf(float f) {
    unsigned u = __float_as_uint(f);
    return (u & 0x80000000u) ? ~u : (u | 0x80000000u);
}
__device__ __forceinline__ float decf(unsigned u) {
    return (u & 0x80000000u) ? __uint_as_float(u ^ 0x80000000u)
                             : __uint_as_float(~u);
}

// ---------------------------------------------------------------------------
// HMMA split-bf16 GEMM: C[M,N] = act(Ahi/lo[M,K] @ Whi/lo[N,K]^T + bias)
// Block tile 128x128, 8 warps (each 32m x 64n), K chunks of 32.
// 3 term passes per chunk: (Ah,Wh), (Al,Wh), (Ah,Wl). fp32 accum in regs.
// mode 0: fp32 out + bias. mode 1: relu(+bias) then split-bf16 out.
// All dims are exact multiples of tiles -> no bounds checks.
// ---------------------------------------------------------------------------
#define SP 40   // padded SMEM row stride (elements)

__global__ __launch_bounds__(256)
void hgemm(const bf16* __restrict__ Ahi, const bf16* __restrict__ Alo,
           const bf16* __restrict__ Whi, const bf16* __restrict__ Wlo,
           const float* __restrict__ bias,
           float* __restrict__ Cf, bf16* __restrict__ Chi, bf16* __restrict__ Clo,
           int Ntot, int K, int mode) {
    __shared__ bf16 sm[4][128][SP];   // planes: 0=Ah 1=Al 2=Wh 3=Wl

    const int tid  = threadIdx.x;
    const int wid  = tid >> 5;
    const int lane = tid & 31;
    const int wm   = wid & 3;         // 4 warp-rows  * 32 = 128 m
    const int wn   = wid >> 2;        // 2 warp-cols  * 64 = 128 n
    const size_t bm = (size_t)blockIdx.x * 128;
    const size_t bn = (size_t)blockIdx.y * 128;

    // per-thread staging coords: each thread loads 2 x uint4 per plane
    const int lr = tid >> 1;          // 0..127
    const int lc = (tid & 1) << 4;    // 0 or 16
    const bf16* pAh = Ahi + (bm + lr) * (size_t)K + lc;
    const bf16* pAl = Alo + (bm + lr) * (size_t)K + lc;
    const bf16* pWh = Whi + (bn + lr) * (size_t)K + lc;
    const bf16* pWl = Wlo + (bn + lr) * (size_t)K + lc;

    // ldmatrix per-thread coords
    const int frow = lane & 15;
    const int fcol = (lane >> 4) << 3;
    const uint32_t sbase = smem_u32(sm);

    float acc[2][8][4];
#pragma unroll
    for (int i = 0; i < 2; i++)
#pragma unroll
        for (int j = 0; j < 8; j++)
#pragma unroll
            for (int q = 0; q < 4; q++) acc[i][j][q] = 0.0f;

    for (int k0 = 0; k0 < K; k0 += 32) {
        // stage all 4 planes (128x32 bf16 each)
        *(uint4*)&sm[0][lr][lc]     = *(const uint4*)(pAh + k0);
        *(uint4*)&sm[0][lr][lc + 8] = *(const uint4*)(pAh + k0 + 8);
        *(uint4*)&sm[1][lr][lc]     = *(const uint4*)(pAl + k0);
        *(uint4*)&sm[1][lr][lc + 8] = *(const uint4*)(pAl + k0 + 8);
        *(uint4*)&sm[2][lr][lc]     = *(const uint4*)(pWh + k0);
        *(uint4*)&sm[2][lr][lc + 8] = *(const uint4*)(pWh + k0 + 8);
        *(uint4*)&sm[3][lr][lc]     = *(const uint4*)(pWl + k0);
        *(uint4*)&sm[3][lr][lc + 8] = *(const uint4*)(pWl + k0 + 8);
        __syncthreads();

#pragma unroll
        for (int pass = 0; pass < 3; pass++) {
            const int ap = (pass == 1) ? 1 : 0;
            const int wp = (pass == 2) ? 3 : 2;
#pragma unroll
            for (int kk = 0; kk < 32; kk += 16) {
                uint32_t a[2][4];
#pragma unroll
                for (int mf = 0; mf < 2; mf++) {
                    uint32_t addr = sbase +
                        (((ap * 128 + wm * 32 + mf * 16 + frow) * SP) + kk + fcol) * 2;
                    ldsm4(a[mf], addr);
                }
#pragma unroll
                for (int g = 0; g < 4; g++) {
                    uint32_t b[4];
                    uint32_t addr = sbase +
                        (((wp * 128 + wn * 64 + g * 16 + frow) * SP) + kk + fcol) * 2;
                    ldsm4(b, addr);
#pragma unroll
                    for (int mf = 0; mf < 2; mf++) {
                        mma16816(acc[mf][g * 2],     a[mf], b[0], b[2]);
                        mma16816(acc[mf][g * 2 + 1], a[mf], b[1], b[3]);
                    }
                }
            }
        }
        __syncthreads();
    }

    // Epilogue. D thread map: row = t/4 (+8 for regs 2,3), col = 2*(t%4)+{0,1}
    const int tr = lane >> 2;
    const int tc = (lane & 3) * 2;
    const size_t m0 = bm + wm * 32;
    const size_t n0 = bn + wn * 64;
#pragma unroll
    for (int mf = 0; mf < 2; mf++) {
#pragma unroll
        for (int hh = 0; hh < 2; hh++) {
            size_t row = m0 + mf * 16 + tr + hh * 8;
#pragma unroll
            for (int nf = 0; nf < 8; nf++) {
                size_t col = n0 + nf * 8 + tc;
                float v0 = acc[mf][nf][hh * 2]     + bias[col];
                float v1 = acc[mf][nf][hh * 2 + 1] + bias[col + 1];
                if (mode == 0) {
                    float2 o; o.x = v0; o.y = v1;
                    *(float2*)&Cf[row * (size_t)Ntot + col] = o;
                } else {
                    v0 = fmaxf(v0, 0.0f);
                    v1 = fmaxf(v1, 0.0f);
                    bf16 h0, l0, h1, l1;
                    splitf(v0, h0, l0);
                    splitf(v1, h1, l1);
                    __nv_bfloat162 hp; hp.x = h0; hp.y = h1;
                    __nv_bfloat162 lp; lp.x = l0; lp.y = l1;
                    *(__nv_bfloat162*)&Chi[row * (size_t)Ntot + col] = hp;
                    *(__nv_bfloat162*)&Clo[row * (size_t)Ntot + col] = lp;
                }
            }
        }
    }
}

// ---------------------------------------------------------------------------
// Weight split kernel (fp32 -> hi/lo bf16 planes)
// ---------------------------------------------------------------------------
__global__ void wsplit_kernel(const float* __restrict__ src,
                              bf16* __restrict__ hi, bf16* __restrict__ lo, int n) {
    int i = blockIdx.x * 256 + threadIdx.x;
    if (i >= n) return;
    bf16 h, l;
    splitf(src[i], h, l);
    hi[i] = h;
    lo[i] = l;
}

// ---------------------------------------------------------------------------
// K0: zero per-launch accumulators
// ---------------------------------------------------------------------------
__global__ void zero_kernel() {
    int i = blockIdx.x * 256 + threadIdx.x;
    if (i < NN * NH * ND) g_ft[i] = 0.0f;
    if (i < NN * NH) { g_s[i] = 0.0f; g_menc[i] = 0u; }
}

// ---------------------------------------------------------------------------
// K1: gather node features (fp32 + split planes)
// ---------------------------------------------------------------------------
__global__ void gather_kernel(const float* __restrict__ feat,
                              const int* __restrict__ emi) {
    int i = blockIdx.x * 256 + threadIdx.x;   // NELT*32 threads exactly
    int r = i >> 5;
    int c = (i & 31) << 2;
    int node = emi[r];
    float4 f = *(const float4*)&feat[(size_t)node * ND + c];
    *(float4*)&g_x[(size_t)r * ND + c] = f;
    bf16 h0, l0, h1, l1, h2, l2, h3, l3;
    splitf(f.x, h0, l0); splitf(f.y, h1, l1);
    splitf(f.z, h2, l2); splitf(f.w, h3, l3);
    __nv_bfloat162 hp0, hp1, lp0, lp1;
    hp0.x = h0; hp0.y = h1; hp1.x = h2; hp1.y = h3;
    lp0.x = l0; lp0.y = l1; lp1.x = l2; lp1.y = l3;
    uint2 hv, lv;
    hv.x = *(uint32_t*)&hp0; hv.y = *(uint32_t*)&hp1;
    lv.x = *(uint32_t*)&lp0; lv.y = *(uint32_t*)&lp1;
    *(uint2*)&g_xh[(size_t)r * ND + c] = hv;
    *(uint2*)&g_xl[(size_t)r * ND + c] = lv;
}

// ---------------------------------------------------------------------------
// K3: tiny attention (L=3, AH=4, HD=32) — one warp per edge; writes planes
// ---------------------------------------------------------------------------
__global__ __launch_bounds__(256)
void attn_kernel() {
    int warp = (blockIdx.x * blockDim.x + threadIdx.x) >> 5;
    int lane = threadIdx.x & 31;
    const float* base = g_qkv + (size_t)warp * NL * 3 * ND;

    float q[NL][NAH], k[NL][NAH], v[NL][NAH];
#pragma unroll
    for (int l = 0; l < NL; l++)
#pragma unroll
        for (int h = 0; h < NAH; h++) {
            q[l][h] = base[l * 384 + h * 32 + lane];
            k[l][h] = base[l * 384 + 128 + h * 32 + lane];
            v[l][h] = base[l * 384 + 256 + h * 32 + lane];
        }

    const float scale = 0.1767766952966369f;
    float o[NL][NAH];
#pragma unroll
    for (int h = 0; h < NAH; h++) {
#pragma unroll
        for (int l = 0; l < NL; l++) {
            float s[NL];
#pragma unroll
            for (int m = 0; m < NL; m++) {
                float p = q[l][h] * k[m][h];
#pragma unroll
                for (int off = 16; off; off >>= 1)
                    p += __shfl_xor_sync(0xFFFFFFFFu, p, off);
                s[m] = p * scale;
            }
            float mx = fmaxf(s[0], fmaxf(s[1], s[2]));
            float e0 = expf(s[0] - mx), e1 = expf(s[1] - mx), e2 = expf(s[2] - mx);
            float inv = 1.0f / (e0 + e1 + e2);
            o[l][h] = (e0 * v[0][h] + e1 * v[1][h] + e2 * v[2][h]) * inv;
        }
    }
#pragma unroll
    for (int l = 0; l < NL; l++)
#pragma unroll
        for (int h = 0; h < NAH; h++) {
            size_t idx = ((size_t)warp * NL + l) * ND + h * 32 + lane;
            bf16 hh, ll;
            splitf(o[l][h], hh, ll);
            g_ah[idx] = hh;
            g_al[idx] = ll;
        }
}

// ---------------------------------------------------------------------------
// K5: x1 = LN1(x + oproj); writes fp32 + split planes
// ---------------------------------------------------------------------------
__global__ __launch_bounds__(256)
void addln_kernel(const float* __restrict__ gam, const float* __restrict__ bet) {
    int warp = (blockIdx.x * blockDim.x + threadIdx.x) >> 5;
    int lane = threadIdx.x & 31;
    const float* xr = g_x + (size_t)warp * ND;
    const float* yr = g_ffo + (size_t)warp * ND;
    float v[4], s = 0.0f;
#pragma unroll
    for (int i = 0; i < 4; i++) {
        v[i] = xr[i * 32 + lane] + yr[i * 32 + lane];
        s += v[i];
    }
#pragma unroll
    for (int off = 16; off; off >>= 1) s += __shfl_xor_sync(0xFFFFFFFFu, s, off);
    float mu = s * (1.0f / 128.0f);
    float vs = 0.0f;
#pragma unroll
    for (int i = 0; i < 4; i++) { float d = v[i] - mu; vs += d * d; }
#pragma unroll
    for (int off = 16; off; off >>= 1) vs += __shfl_xor_sync(0xFFFFFFFFu, vs, off);
    float inv = rsqrtf(vs * (1.0f / 128.0f) + 1e-5f);
#pragma unroll
    for (int i = 0; i < 4; i++) {
        size_t idx = (size_t)warp * ND + i * 32 + lane;
        float r = (v[i] - mu) * inv * gam[i * 32 + lane] + bet[i * 32 + lane];
        g_x1[idx] = r;
        bf16 h, l;
        splitf(r, h, l);
        g_x1h[idx] = h;
        g_x1l[idx] = l;
    }
}

// ---------------------------------------------------------------------------
// K7: LN2 + mean over L -> hidden planes
// ---------------------------------------------------------------------------
__global__ __launch_bounds__(256)
void ln2hidden_kernel(const float* __restrict__ gam, const float* __restrict__ bet) {
    int warp = (blockIdx.x * blockDim.x + threadIdx.x) >> 5;
    int lane = threadIdx.x & 31;
    float hid[4] = {0, 0, 0, 0};
#pragma unroll
    for (int l = 0; l < NL; l++) {
        size_t r = (size_t)warp * NL + l;
        const float* xr = g_x1 + r * ND;
        const float* yr = g_ffo + r * ND;
        float v[4], s = 0.0f;
#pragma unroll
        for (int i = 0; i < 4; i++) {
            v[i] = xr[i * 32 + lane] + yr[i * 32 + lane];
            s += v[i];
        }
#pragma unroll
        for (int off = 16; off; off >>= 1) s += __shfl_xor_sync(0xFFFFFFFFu, s, off);
        float mu = s * (1.0f / 128.0f);
        float vs = 0.0f;
#pragma unroll
        for (int i = 0; i < 4; i++) { float d = v[i] - mu; vs += d * d; }
#pragma unroll
        for (int off = 16; off; off >>= 1) vs += __shfl_xor_sync(0xFFFFFFFFu, vs, off);
        float inv = rsqrtf(vs * (1.0f / 128.0f) + 1e-5f);
#pragma unroll
        for (int i = 0; i < 4; i++)
            hid[i] += ((v[i] - mu) * inv * gam[i * 32 + lane] + bet[i * 32 + lane])
                      * (1.0f / 3.0f);
    }
#pragma unroll
    for (int i = 0; i < 4; i++) {
        size_t idx = (size_t)warp * ND + i * 32 + lane;
        bf16 h, l;
        splitf(hid[i], h, l);
        g_hidh[idx] = h;
        g_hidl[idx] = l;
    }
}

// ---------------------------------------------------------------------------
// K9: per-edge logits + leaky relu + segment atomicMax
// ---------------------------------------------------------------------------
__global__ __launch_bounds__(256)
void amax_kernel(const float* __restrict__ feat, const int* __restrict__ emi,
                 const int* __restrict__ dst, const float* __restrict__ a1w,
                 const float* __restrict__ a2) {
    int warp = (blockIdx.x * blockDim.x + threadIdx.x) >> 5;
    int lane = threadIdx.x & 31;
    int node = emi[warp * NL + (NL - 1)];
    int d = dst[warp];
    float c[4];
#pragma unroll
    for (int i = 0; i < 4; i++) c[i] = feat[(size_t)node * ND + i * 32 + lane];
#pragma unroll
    for (int h = 0; h < NH; h++) {
        const float* w   = a1w + h * ND;
        const float* efr = g_eft + (size_t)warp * (NH * ND) + h * ND;
        const float* at2 = a2 + h * ND;
        float p = 0.0f;
#pragma unroll
        for (int i = 0; i < 4; i++)
            p += c[i] * w[i * 32 + lane] + efr[i * 32 + lane] * at2[i * 32 + lane];
#pragma unroll
        for (int off = 16; off; off >>= 1) p += __shfl_xor_sync(0xFFFFFFFFu, p, off);
        if (lane == 0) {
            float av = p > 0.0f ? p : 0.01f * p;
            g_a[warp * NH + h] = av;
            atomicMax(&g_menc[d * NH + h], encf(av));
        }
    }
}

// ---------------------------------------------------------------------------
// K10: e = exp(a - m[dst]); segment sum
// ---------------------------------------------------------------------------
__global__ void exps_kernel(const int* __restrict__ dst) {
    int i = blockIdx.x * 256 + threadIdx.x;
    int e = i >> 3, h = i & 7;
    int d = dst[e];
    float m = decf(g_menc[d * NH + h]);
    float ex = expf(g_a[i] - m);
    g_expa[i] = ex;
    atomicAdd(&g_s[d * NH + h], ex);
}

// ---------------------------------------------------------------------------
// K11: ft[dst] += eft * (e / s[dst])
// ---------------------------------------------------------------------------
__global__ void ftacc_kernel(const int* __restrict__ dst) {
    size_t i = (size_t)blockIdx.x * 256 + threadIdx.x;
    int e = (int)(i >> 10);
    int j = (int)(i & 1023);
    int h = j >> 7;
    int d = dst[e];
    float w = g_expa[e * NH + h] / g_s[d * NH + h];
    atomicAdd(&g_ft[(size_t)d * (NH * ND) + j], g_eft[i] * w);
}

// ---------------------------------------------------------------------------
// K12: out = ft[target_idx]
// ---------------------------------------------------------------------------
__global__ void outg_kernel(const int* __restrict__ tgt, float* __restrict__ out) {
    size_t i = (size_t)blockIdx.x * 256 + threadIdx.x;
    int t = (int)(i >> 10);
    int j = (int)(i & 1023);
    out[i] = g_ft[(size_t)tgt[t] * (NH * ND) + j];
}

// ---------------------------------------------------------------------------
extern "C" void kernel_launch(void* const* d_in, const int* in_sizes, int n_in,
                              void* d_out, int out_size) {
    const float* features = (const float*)d_in[0];
    const int*   emi      = (const int*)d_in[1];
    const int*   dst      = (const int*)d_in[2];
    const int*   tgt      = (const int*)d_in[3];
    const float* in_w     = (const float*)d_in[4];
    const float* in_b     = (const float*)d_in[5];
    const float* out_w    = (const float*)d_in[6];
    const float* out_b    = (const float*)d_in[7];
    const float* ln1_g    = (const float*)d_in[8];
    const float* ln1_b    = (const float*)d_in[9];
    const float* w1       = (const float*)d_in[10];
    const float* b1       = (const float*)d_in[11];
    const float* w2       = (const float*)d_in[12];
    const float* b2       = (const float*)d_in[13];
    const float* ln2_g    = (const float*)d_in[14];
    const float* ln2_b    = (const float*)d_in[15];
    const float* rnn_w    = (const float*)d_in[16];
    const float* rnn_b    = (const float*)d_in[17];
    const float* a1w      = (const float*)d_in[18];
    const float* a2       = (const float*)d_in[19];
    float* out = (float*)d_out;

    // Resolve device-global addresses (query-only; capture safe)
    float *pqkv, *pffo, *peft;
    bf16 *pxh, *pxl, *pah, *pal, *px1h, *px1l, *phh, *phl, *phidh, *phidl;
    bf16 *piwh, *piwl, *powh, *powl, *pw1h, *pw1l, *pw2h, *pw2l, *prwh, *prwl;
    cudaGetSymbolAddress((void**)&pqkv,  g_qkv);
    cudaGetSymbolAddress((void**)&pffo,  g_ffo);
    cudaGetSymbolAddress((void**)&peft,  g_eft);
    cudaGetSymbolAddress((void**)&pxh,   g_xh);
    cudaGetSymbolAddress((void**)&pxl,   g_xl);
    cudaGetSymbolAddress((void**)&pah,   g_ah);
    cudaGetSymbolAddress((void**)&pal,   g_al);
    cudaGetSymbolAddress((void**)&px1h,  g_x1h);
    cudaGetSymbolAddress((void**)&px1l,  g_x1l);
    cudaGetSymbolAddress((void**)&phh,   g_hh);
    cudaGetSymbolAddress((void**)&phl,   g_hl);
    cudaGetSymbolAddress((void**)&phidh, g_hidh);
    cudaGetSymbolAddress((void**)&phidl, g_hidl);
    cudaGetSymbolAddress((void**)&piwh,  g_iwh);
    cudaGetSymbolAddress((void**)&piwl,  g_iwl);
    cudaGetSymbolAddress((void**)&powh,  g_owh);
    cudaGetSymbolAddress((void**)&powl,  g_owl);
    cudaGetSymbolAddress((void**)&pw1h,  g_w1h);
    cudaGetSymbolAddress((void**)&pw1l,  g_w1l);
    cudaGetSymbolAddress((void**)&pw2h,  g_w2h);
    cudaGetSymbolAddress((void**)&pw2l,  g_w2l);
    cudaGetSymbolAddress((void**)&prwh,  g_rwh);
    cudaGetSymbolAddress((void**)&prwl,  g_rwl);

    // Split weights into bf16 hi/lo planes
    wsplit_kernel<<<(3 * ND * ND + 255) / 256, 256>>>(in_w,  piwh, piwl, 3 * ND * ND);
    wsplit_kernel<<<(ND * ND + 255) / 256, 256>>>(out_w, powh, powl, ND * ND);
    wsplit_kernel<<<(NFF * ND + 255) / 256, 256>>>(w1,   pw1h, pw1l, NFF * ND);
    wsplit_kernel<<<(ND * NFF + 255) / 256, 256>>>(w2,   pw2h, pw2l, ND * NFF);
    wsplit_kernel<<<(NH * ND * ND + 255) / 256, 256>>>(rnn_w, prwh, prwl, NH * ND * ND);

    // K0: zero accumulators
    zero_kernel<<<(NN * NH * ND + 255) / 256, 256>>>();

    // K1: gather features
    gather_kernel<<<NELT * 32 / 256, 256>>>(features, emi);

    // K2: QKV = x @ in_w^T + in_b : [196608,128]x[384,128]
    hgemm<<<dim3(NELT / 128, 3), 256>>>(
        pxh, pxl, piwh, piwl, in_b, pqkv, nullptr, nullptr, 384, ND, 0);

    // K3: attention -> planes
    attn_kernel<<<NE / 8, 256>>>();

    // K4: out projection -> g_ffo fp32
    hgemm<<<dim3(NELT / 128, 1), 256>>>(
        pah, pal, powh, powl, out_b, pffo, nullptr, nullptr, ND, ND, 0);

    // K5: x1 = LN1(x + oproj)
    addln_kernel<<<NELT / 8, 256>>>(ln1_g, ln1_b);

    // K6: FFN in 4 M-chunks (hidden planes are CH x 2048 each)
    for (int c = 0; c < NELT / CH; c++) {
        const bf16* Ah = px1h + (size_t)c * CH * ND;
        const bf16* Al = px1l + (size_t)c * CH * ND;
        float* Cout = pffo + (size_t)c * CH * ND;
        // FFN1 = relu(x1 @ w1^T + b1) -> split planes h
        hgemm<<<dim3(CH / 128, NFF / 128), 256>>>(
            Ah, Al, pw1h, pw1l, b1, nullptr, phh, phl, NFF, ND, 1);
        // FFN2 = h @ w2^T + b2 -> g_ffo fp32
        hgemm<<<dim3(CH / 128, 1), 256>>>(
            phh, phl, pw2h, pw2l, b2, Cout, nullptr, nullptr, ND, NFF, 0);
    }

    // K7: x2 = LN2(x1 + ff); hidden = mean_L(x2) -> planes
    ln2hidden_kernel<<<NE / 8, 256>>>(ln2_g, ln2_b);

    // K8: eft = hidden @ rnn_w^T + rnn_b : [65536,128]x[1024,128]
    hgemm<<<dim3(NE / 128, (NH * ND) / 128), 256>>>(
        phidh, phidl, prwh, prwl, rnn_b, peft, nullptr, nullptr, NH * ND, ND, 0);

    // K9-K12: segment softmax aggregation + output gather
    amax_kernel<<<NE / 8, 256>>>(features, emi, dst, a1w, a2);
    exps_kernel<<<NE * NH / 256, 256>>>(dst);
    ftacc_kernel<<<(int)((size_t)NE * NH * ND / 256), 256>>>(dst);
    outg_kernel<<<(int)((size_t)NT * NH * ND / 256), 256>>>(tgt, out);
}

// round 6
// speedup vs baseline: 2.9332x; 1.3565x over previous
#include <cuda_runtime.h>
#include <cuda_bf16.h>
#include <cstdint>
#include <math.h>

// Problem constants
#define NE    65536      // edges
#define NL    3          // metapath length
#define NELT  196608     // NE*NL tokens
#define NN    20000      // nodes
#define NT    16384      // targets
#define ND    128        // model dim
#define NFF   2048       // FF dim
#define NAH   4          // attention heads
#define NH    8          // output heads
#define FFC   512        // FFN hidden N-chunk width (NFF/4)

typedef __nv_bfloat16 bf16;

// ---------------------------------------------------------------------------
// Static device scratch (~1.70 GB total; must stay < 2 GB or host link fails
// with GOTPCREL relocation overflow — learned in R4)
// ---------------------------------------------------------------------------
__device__ float g_x     [(size_t)NELT * ND];        // gathered features fp32
__device__ bf16  g_xh    [(size_t)NELT * ND];        // split planes of x
__device__ bf16  g_xl    [(size_t)NELT * ND];
__device__ float g_qkv   [(size_t)NELT * 3 * ND];    // qkv projection fp32
__device__ bf16  g_ah    [(size_t)NELT * ND];        // attention out planes
__device__ bf16  g_al    [(size_t)NELT * ND];
__device__ float g_x1    [(size_t)NELT * ND];        // post-LN1 fp32
__device__ bf16  g_x1h   [(size_t)NELT * ND];
__device__ bf16  g_x1l   [(size_t)NELT * ND];
__device__ bf16  g_hh    [(size_t)NELT * FFC];       // FFN hidden planes (N-chunked)
__device__ bf16  g_hl    [(size_t)NELT * FFC];
__device__ float g_ffo   [(size_t)NELT * ND];        // outproj out, then FFN out
__device__ bf16  g_hidh  [(size_t)NE * ND];          // hidden (mean over L)
__device__ bf16  g_hidl  [(size_t)NE * ND];
__device__ float g_eft   [(size_t)NE * NH * ND];     // rnn projection fp32
__device__ float g_a     [(size_t)NE * NH];
__device__ float g_expa  [(size_t)NE * NH];
__device__ unsigned g_menc[(size_t)NN * NH];
__device__ float g_s     [(size_t)NN * NH];
__device__ float g_ft    [(size_t)NN * NH * ND];
// weight planes
__device__ bf16 g_iwh[3 * ND * ND], g_iwl[3 * ND * ND];
__device__ bf16 g_owh[ND * ND],     g_owl[ND * ND];
__device__ bf16 g_w1h[NFF * ND],    g_w1l[NFF * ND];
__device__ bf16 g_w2h[ND * NFF],    g_w2l[ND * NFF];
__device__ bf16 g_rwh[NH * ND * ND],g_rwl[NH * ND * ND];

// ---------------------------------------------------------------------------
// Helpers
// ---------------------------------------------------------------------------
__device__ __forceinline__ uint32_t smem_u32(const void* p) {
    uint32_t a;
    asm("{ .reg .u64 t; cvta.to.shared.u64 t, %1; cvt.u32.u64 %0, t; }" : "=r"(a) : "l"(p));
    return a;
}
__device__ __forceinline__ void ldsm4(uint32_t* r, uint32_t addr) {
    asm volatile("ldmatrix.sync.aligned.m8n8.x4.shared.b16 {%0,%1,%2,%3}, [%4];"
                 : "=r"(r[0]), "=r"(r[1]), "=r"(r[2]), "=r"(r[3]) : "r"(addr));
}
__device__ __forceinline__ void mma16816(float* c, const uint32_t* a,
                                         uint32_t b0, uint32_t b1) {
    asm volatile("mma.sync.aligned.m16n8k16.row.col.f32.bf16.bf16.f32 "
                 "{%0,%1,%2,%3}, {%4,%5,%6,%7}, {%8,%9}, {%0,%1,%2,%3};"
                 : "+f"(c[0]), "+f"(c[1]), "+f"(c[2]), "+f"(c[3])
                 : "r"(a[0]), "r"(a[1]), "r"(a[2]), "r"(a[3]), "r"(b0), "r"(b1));
}
__device__ __forceinline__ void cpa16(uint32_t saddr, const void* g) {
    asm volatile("cp.async.cg.shared.global [%0], [%1], 16;" :: "r"(saddr), "l"(g));
}
#define CPA_COMMIT() asm volatile("cp.async.commit_group;" ::: "memory")
#define CPA_WAIT0()  asm volatile("cp.async.wait_group 0;" ::: "memory")

__device__ __forceinline__ void splitf(float v, bf16& h, bf16& l) {
    h = __float2bfloat16(v);
    l = __float2bfloat16(v - __bfloat162float(h));
}
__device__ __forceinline__ unsigned encf(float f) {
    unsigned u = __float_as_uint(f);
    return (u & 0x80000000u) ? ~u : (u | 0x80000000u);
}
__device__ __forceinline__ float decf(unsigned u) {
    return (u & 0x80000000u) ? __uint_as_float(u ^ 0x80000000u)
                             : __uint_as_float(~u);
}

// ---------------------------------------------------------------------------
// HMMA split-bf16 GEMM, double-buffered cp.async pipeline.
// C[M,N] = act(Ahi/lo[M,K](lda) @ Whi/lo[N,K](ldw)^T + bias)
// Block tile 128x128, 8 warps (each 32m x 64n), K chunks of 32.
// 3 term passes per chunk: (Ah,Wh), (Al,Wh), (Ah,Wl). fp32 accum in regs.
// mode 0: Cf = acc + bias.  mode 1: relu(acc+bias) -> split bf16 planes.
// mode 2: Cf += acc (accumulate, no bias).
// All dims are exact multiples of tiles -> no bounds checks.
// ---------------------------------------------------------------------------
#define SP 40                                   // padded SMEM row stride (elems)
#define PLS  (128 * SP * 2)                     // plane stride bytes (10240)
#define BUFS (4 * PLS)                          // buffer stride bytes (40960)
#define HG_SMEM (2 * BUFS)                      // 81920 bytes dynamic SMEM

__global__ __launch_bounds__(256)
void hgemm(const bf16* __restrict__ Ahi, const bf16* __restrict__ Alo, int lda,
           const bf16* __restrict__ Whi, const bf16* __restrict__ Wlo, int ldw,
           const float* __restrict__ bias,
           float* __restrict__ Cf, bf16* __restrict__ Chi, bf16* __restrict__ Clo,
           int ldc, int K, int mode) {
    extern __shared__ bf16 smdyn[];
    const uint32_t sbase = smem_u32(smdyn);

    const int tid  = threadIdx.x;
    const int wid  = tid >> 5;
    const int lane = tid & 31;
    const int wm   = wid & 3;
    const int wn   = wid >> 2;
    const size_t bm = (size_t)blockIdx.x * 128;
    const size_t bn = (size_t)blockIdx.y * 128;

    // staging coords: each thread cp.asyncs 2x16B per plane per chunk
    const int lr = tid >> 1;          // 0..127
    const int lc = (tid & 1) << 4;    // 0 or 16
    const bf16* s0 = Ahi + (bm + lr) * (size_t)lda + lc;
    const bf16* s1 = Alo + (bm + lr) * (size_t)lda + lc;
    const bf16* s2 = Whi + (bn + lr) * (size_t)ldw + lc;
    const bf16* s3 = Wlo + (bn + lr) * (size_t)ldw + lc;
    const uint32_t dstb = sbase + (lr * SP + lc) * 2;

    // ldmatrix coords
    const int frow = lane & 15;
    const int fcol = (lane >> 4) << 3;

    float acc[2][8][4];
#pragma unroll
    for (int i = 0; i < 2; i++)
#pragma unroll
        for (int j = 0; j < 8; j++)
#pragma unroll
            for (int q = 0; q < 4; q++) acc[i][j][q] = 0.0f;

    const int nch = K >> 5;

    // prefetch chunk 0 into buffer 0
    {
        cpa16(dstb,                s0); cpa16(dstb + 16,                s0 + 8);
        cpa16(dstb + PLS,          s1); cpa16(dstb + PLS + 16,          s1 + 8);
        cpa16(dstb + 2 * PLS,      s2); cpa16(dstb + 2 * PLS + 16,      s2 + 8);
        cpa16(dstb + 3 * PLS,      s3); cpa16(dstb + 3 * PLS + 16,      s3 + 8);
        CPA_COMMIT();
    }

    for (int c = 0; c < nch; c++) {
        CPA_WAIT0();
        __syncthreads();
        if (c + 1 < nch) {
            const int ko = (c + 1) << 5;
            const uint32_t d = dstb + ((c + 1) & 1) * BUFS;
            cpa16(d,               s0 + ko); cpa16(d + 16,               s0 + ko + 8);
            cpa16(d + PLS,         s1 + ko); cpa16(d + PLS + 16,         s1 + ko + 8);
            cpa16(d + 2 * PLS,     s2 + ko); cpa16(d + 2 * PLS + 16,     s2 + ko + 8);
            cpa16(d + 3 * PLS,     s3 + ko); cpa16(d + 3 * PLS + 16,     s3 + ko + 8);
            CPA_COMMIT();
        }
        const uint32_t cb = sbase + (c & 1) * BUFS;
#pragma unroll
        for (int pass = 0; pass < 3; pass++) {
            const int ap = (pass == 1) ? 1 : 0;
            const int wp = (pass == 2) ? 3 : 2;
#pragma unroll
            for (int kk = 0; kk < 32; kk += 16) {
                uint32_t a[2][4];
#pragma unroll
                for (int mf = 0; mf < 2; mf++)
                    ldsm4(a[mf], cb + ap * PLS +
                          ((wm * 32 + mf * 16 + frow) * SP + kk + fcol) * 2);
#pragma unroll
                for (int g = 0; g < 4; g++) {
                    uint32_t b[4];
                    ldsm4(b, cb + wp * PLS +
                          ((wn * 64 + g * 16 + frow) * SP + kk + fcol) * 2);
#pragma unroll
                    for (int mf = 0; mf < 2; mf++) {
                        mma16816(acc[mf][g * 2],     a[mf], b[0], b[2]);
                        mma16816(acc[mf][g * 2 + 1], a[mf], b[1], b[3]);
                    }
                }
            }
        }
    }

    // Epilogue. D thread map: row = t/4 (+8 for regs 2,3), col = 2*(t%4)+{0,1}
    const int tr = lane >> 2;
    const int tc = (lane & 3) * 2;
    const size_t m0 = bm + wm * 32;
    const size_t n0 = bn + wn * 64;
#pragma unroll
    for (int mf = 0; mf < 2; mf++) {
#pragma unroll
        for (int hh = 0; hh < 2; hh++) {
            size_t row = m0 + mf * 16 + tr + hh * 8;
#pragma unroll
            for (int nf = 0; nf < 8; nf++) {
                size_t col = n0 + nf * 8 + tc;
                float a0 = acc[mf][nf][hh * 2];
                float a1 = acc[mf][nf][hh * 2 + 1];
                if (mode == 0) {
                    float2 o;
                    o.x = a0 + bias[col];
                    o.y = a1 + bias[col + 1];
                    *(float2*)&Cf[row * (size_t)ldc + col] = o;
                } else if (mode == 2) {
                    float2 old = *(float2*)&Cf[row * (size_t)ldc + col];
                    old.x += a0;
                    old.y += a1;
                    *(float2*)&Cf[row * (size_t)ldc + col] = old;
                } else {
                    float v0 = fmaxf(a0 + bias[col], 0.0f);
                    float v1 = fmaxf(a1 + bias[col + 1], 0.0f);
                    bf16 h0, l0, h1, l1;
                    splitf(v0, h0, l0);
                    splitf(v1, h1, l1);
                    __nv_bfloat162 hp; hp.x = h0; hp.y = h1;
                    __nv_bfloat162 lp; lp.x = l0; lp.y = l1;
                    *(__nv_bfloat162*)&Chi[row * (size_t)ldc + col] = hp;
                    *(__nv_bfloat162*)&Clo[row * (size_t)ldc + col] = lp;
                }
            }
        }
    }
}

// ---------------------------------------------------------------------------
// Fused weight split (all 5 weight tensors in one launch)
// ---------------------------------------------------------------------------
#define WN0 (3 * ND * ND)
#define WN1 (WN0 + ND * ND)
#define WN2 (WN1 + NFF * ND)
#define WN3 (WN2 + ND * NFF)
#define WN4 (WN3 + NH * ND * ND)

__global__ void wsplit_all(const float* __restrict__ in_w,
                           const float* __restrict__ out_w,
                           const float* __restrict__ w1,
                           const float* __restrict__ w2,
                           const float* __restrict__ rnn_w) {
    int i = blockIdx.x * 256 + threadIdx.x;
    if (i >= WN4) return;
    const float* s; bf16 *h, *l; int j;
    if (i < WN0)      { s = in_w;  h = g_iwh; l = g_iwl; j = i; }
    else if (i < WN1) { s = out_w; h = g_owh; l = g_owl; j = i - WN0; }
    else if (i < WN2) { s = w1;    h = g_w1h; l = g_w1l; j = i - WN1; }
    else if (i < WN3) { s = w2;    h = g_w2h; l = g_w2l; j = i - WN2; }
    else              { s = rnn_w; h = g_rwh; l = g_rwl; j = i - WN3; }
    bf16 hh, ll;
    splitf(s[j], hh, ll);
    h[j] = hh;
    l[j] = ll;
}

// ---------------------------------------------------------------------------
// K0: zero per-launch accumulators
// ---------------------------------------------------------------------------
__global__ void zero_kernel() {
    int i = blockIdx.x * 256 + threadIdx.x;
    if (i < NN * NH * ND) g_ft[i] = 0.0f;
    if (i < NN * NH) { g_s[i] = 0.0f; g_menc[i] = 0u; }
}

// ---------------------------------------------------------------------------
// K1: gather node features (fp32 + split planes)
// ---------------------------------------------------------------------------
__global__ void gather_kernel(const float* __restrict__ feat,
                              const int* __restrict__ emi) {
    int i = blockIdx.x * 256 + threadIdx.x;   // NELT*32 threads exactly
    int r = i >> 5;
    int c = (i & 31) << 2;
    int node = emi[r];
    float4 f = *(const float4*)&feat[(size_t)node * ND + c];
    *(float4*)&g_x[(size_t)r * ND + c] = f;
    bf16 h0, l0, h1, l1, h2, l2, h3, l3;
    splitf(f.x, h0, l0); splitf(f.y, h1, l1);
    splitf(f.z, h2, l2); splitf(f.w, h3, l3);
    __nv_bfloat162 hp0, hp1, lp0, lp1;
    hp0.x = h0; hp0.y = h1; hp1.x = h2; hp1.y = h3;
    lp0.x = l0; lp0.y = l1; lp1.x = l2; lp1.y = l3;
    uint2 hv, lv;
    hv.x = *(uint32_t*)&hp0; hv.y = *(uint32_t*)&hp1;
    lv.x = *(uint32_t*)&lp0; lv.y = *(uint32_t*)&lp1;
    *(uint2*)&g_xh[(size_t)r * ND + c] = hv;
    *(uint2*)&g_xl[(size_t)r * ND + c] = lv;
}

// ---------------------------------------------------------------------------
// K3: tiny attention (L=3, AH=4, HD=32) — one warp per edge; writes planes
// ---------------------------------------------------------------------------
__global__ __launch_bounds__(256)
void attn_kernel() {
    int warp = (blockIdx.x * blockDim.x + threadIdx.x) >> 5;
    int lane = threadIdx.x & 31;
    const float* base = g_qkv + (size_t)warp * NL * 3 * ND;

    float q[NL][NAH], k[NL][NAH], v[NL][NAH];
#pragma unroll
    for (int l = 0; l < NL; l++)
#pragma unroll
        for (int h = 0; h < NAH; h++) {
            q[l][h] = base[l * 384 + h * 32 + lane];
            k[l][h] = base[l * 384 + 128 + h * 32 + lane];
            v[l][h] = base[l * 384 + 256 + h * 32 + lane];
        }

    const float scale = 0.1767766952966369f;
    float o[NL][NAH];
#pragma unroll
    for (int h = 0; h < NAH; h++) {
#pragma unroll
        for (int l = 0; l < NL; l++) {
            float s[NL];
#pragma unroll
            for (int m = 0; m < NL; m++) {
                float p = q[l][h] * k[m][h];
#pragma unroll
                for (int off = 16; off; off >>= 1)
                    p += __shfl_xor_sync(0xFFFFFFFFu, p, off);
                s[m] = p * scale;
            }
            float mx = fmaxf(s[0], fmaxf(s[1], s[2]));
            float e0 = expf(s[0] - mx), e1 = expf(s[1] - mx), e2 = expf(s[2] - mx);
            float inv = 1.0f / (e0 + e1 + e2);
            o[l][h] = (e0 * v[0][h] + e1 * v[1][h] + e2 * v[2][h]) * inv;
        }
    }
#pragma unroll
    for (int l = 0; l < NL; l++)
#pragma unroll
        for (int h = 0; h < NAH; h++) {
            size_t idx = ((size_t)warp * NL + l) * ND + h * 32 + lane;
            bf16 hh, ll;
            splitf(o[l][h], hh, ll);
            g_ah[idx] = hh;
            g_al[idx] = ll;
        }
}

// ---------------------------------------------------------------------------
// K5: x1 = LN1(x + oproj); writes fp32 + split planes
// ---------------------------------------------------------------------------
__global__ __launch_bounds__(256)
void addln_kernel(const float* __restrict__ gam, const float* __restrict__ bet) {
    int warp = (blockIdx.x * blockDim.x + threadIdx.x) >> 5;
    int lane = threadIdx.x & 31;
    const float* xr = g_x + (size_t)warp * ND;
    const float* yr = g_ffo + (size_t)warp * ND;
    float v[4], s = 0.0f;
#pragma unroll
    for (int i = 0; i < 4; i++) {
        v[i] = xr[i * 32 + lane] + yr[i * 32 + lane];
        s += v[i];
    }
#pragma unroll
    for (int off = 16; off; off >>= 1) s += __shfl_xor_sync(0xFFFFFFFFu, s, off);
    float mu = s * (1.0f / 128.0f);
    float vs = 0.0f;
#pragma unroll
    for (int i = 0; i < 4; i++) { float d = v[i] - mu; vs += d * d; }
#pragma unroll
    for (int off = 16; off; off >>= 1) vs += __shfl_xor_sync(0xFFFFFFFFu, vs, off);
    float inv = rsqrtf(vs * (1.0f / 128.0f) + 1e-5f);
#pragma unroll
    for (int i = 0; i < 4; i++) {
        size_t idx = (size_t)warp * ND + i * 32 + lane;
        float r = (v[i] - mu) * inv * gam[i * 32 + lane] + bet[i * 32 + lane];
        g_x1[idx] = r;
        bf16 h, l;
        splitf(r, h, l);
        g_x1h[idx] = h;
        g_x1l[idx] = l;
    }
}

// ---------------------------------------------------------------------------
// K7: LN2 + mean over L -> hidden planes
// ---------------------------------------------------------------------------
__global__ __launch_bounds__(256)
void ln2hidden_kernel(const float* __restrict__ gam, const float* __restrict__ bet) {
    int warp = (blockIdx.x * blockDim.x + threadIdx.x) >> 5;
    int lane = threadIdx.x & 31;
    float hid[4] = {0, 0, 0, 0};
#pragma unroll
    for (int l = 0; l < NL; l++) {
        size_t r = (size_t)warp * NL + l;
        const float* xr = g_x1 + r * ND;
        const float* yr = g_ffo + r * ND;
        float v[4], s = 0.0f;
#pragma unroll
        for (int i = 0; i < 4; i++) {
            v[i] = xr[i * 32 + lane] + yr[i * 32 + lane];
            s += v[i];
        }
#pragma unroll
        for (int off = 16; off; off >>= 1) s += __shfl_xor_sync(0xFFFFFFFFu, s, off);
        float mu = s * (1.0f / 128.0f);
        float vs = 0.0f;
#pragma unroll
        for (int i = 0; i < 4; i++) { float d = v[i] - mu; vs += d * d; }
#pragma unroll
        for (int off = 16; off; off >>= 1) vs += __shfl_xor_sync(0xFFFFFFFFu, vs, off);
        float inv = rsqrtf(vs * (1.0f / 128.0f) + 1e-5f);
#pragma unroll
        for (int i = 0; i < 4; i++)
            hid[i] += ((v[i] - mu) * inv * gam[i * 32 + lane] + bet[i * 32 + lane])
                      * (1.0f / 3.0f);
    }
#pragma unroll
    for (int i = 0; i < 4; i++) {
        size_t idx = (size_t)warp * ND + i * 32 + lane;
        bf16 h, l;
        splitf(hid[i], h, l);
        g_hidh[idx] = h;
        g_hidl[idx] = l;
    }
}

// ---------------------------------------------------------------------------
// K9: per-edge logits + leaky relu + segment atomicMax
// ---------------------------------------------------------------------------
__global__ __launch_bounds__(256)
void amax_kernel(const float* __restrict__ feat, const int* __restrict__ emi,
                 const int* __restrict__ dst, const float* __restrict__ a1w,
                 const float* __restrict__ a2) {
    int warp = (blockIdx.x * blockDim.x + threadIdx.x) >> 5;
    int lane = threadIdx.x & 31;
    int node = emi[warp * NL + (NL - 1)];
    int d = dst[warp];
    float c[4];
#pragma unroll
    for (int i = 0; i < 4; i++) c[i] = feat[(size_t)node * ND + i * 32 + lane];
#pragma unroll
    for (int h = 0; h < NH; h++) {
        const float* w   = a1w + h * ND;
        const float* efr = g_eft + (size_t)warp * (NH * ND) + h * ND;
        const float* at2 = a2 + h * ND;
        float p = 0.0f;
#pragma unroll
        for (int i = 0; i < 4; i++)
            p += c[i] * w[i * 32 + lane] + efr[i * 32 + lane] * at2[i * 32 + lane];
#pragma unroll
        for (int off = 16; off; off >>= 1) p += __shfl_xor_sync(0xFFFFFFFFu, p, off);
        if (lane == 0) {
            float av = p > 0.0f ? p : 0.01f * p;
            g_a[warp * NH + h] = av;
            atomicMax(&g_menc[d * NH + h], encf(av));
        }
    }
}

// ---------------------------------------------------------------------------
// K10: e = exp(a - m[dst]); segment sum
// ---------------------------------------------------------------------------
__global__ void exps_kernel(const int* __restrict__ dst) {
    int i = blockIdx.x * 256 + threadIdx.x;
    int e = i >> 3, h = i & 7;
    int d = dst[e];
    float m = decf(g_menc[d * NH + h]);
    float ex = expf(g_a[i] - m);
    g_expa[i] = ex;
    atomicAdd(&g_s[d * NH + h], ex);
}

// ---------------------------------------------------------------------------
// K11: ft[dst] += eft * (e / s[dst])
// ---------------------------------------------------------------------------
__global__ void ftacc_kernel(const int* __restrict__ dst) {
    size_t i = (size_t)blockIdx.x * 256 + threadIdx.x;
    int e = (int)(i >> 10);
    int j = (int)(i & 1023);
    int h = j >> 7;
    int d = dst[e];
    float w = g_expa[e * NH + h] / g_s[d * NH + h];
    atomicAdd(&g_ft[(size_t)d * (NH * ND) + j], g_eft[i] * w);
}

// ---------------------------------------------------------------------------
// K12: out = ft[target_idx]
// ---------------------------------------------------------------------------
__global__ void outg_kernel(const int* __restrict__ tgt, float* __restrict__ out) {
    size_t i = (size_t)blockIdx.x * 256 + threadIdx.x;
    int t = (int)(i >> 10);
    int j = (int)(i & 1023);
    out[i] = g_ft[(size_t)tgt[t] * (NH * ND) + j];
}

// ---------------------------------------------------------------------------
extern "C" void kernel_launch(void* const* d_in, const int* in_sizes, int n_in,
                              void* d_out, int out_size) {
    const float* features = (const float*)d_in[0];
    const int*   emi      = (const int*)d_in[1];
    const int*   dst      = (const int*)d_in[2];
    const int*   tgt      = (const int*)d_in[3];
    const float* in_w     = (const float*)d_in[4];
    const float* in_b     = (const float*)d_in[5];
    const float* out_w    = (const float*)d_in[6];
    const float* out_b    = (const float*)d_in[7];
    const float* ln1_g    = (const float*)d_in[8];
    const float* ln1_b    = (const float*)d_in[9];
    const float* w1       = (const float*)d_in[10];
    const float* b1       = (const float*)d_in[11];
    const float* w2       = (const float*)d_in[12];
    const float* b2       = (const float*)d_in[13];
    const float* ln2_g    = (const float*)d_in[14];
    const float* ln2_b    = (const float*)d_in[15];
    const float* rnn_w    = (const float*)d_in[16];
    const float* rnn_b    = (const float*)d_in[17];
    const float* a1w      = (const float*)d_in[18];
    const float* a2       = (const float*)d_in[19];
    float* out = (float*)d_out;

    cudaFuncSetAttribute(hgemm, cudaFuncAttributeMaxDynamicSharedMemorySize, HG_SMEM);

    // Resolve device-global addresses (query-only; capture safe)
    float *pqkv, *pffo, *peft;
    bf16 *pxh, *pxl, *pah, *pal, *px1h, *px1l, *phh, *phl, *phidh, *phidl;
    bf16 *piwh, *piwl, *powh, *powl, *pw1h, *pw1l, *pw2h, *pw2l, *prwh, *prwl;
    cudaGetSymbolAddress((void**)&pqkv,  g_qkv);
    cudaGetSymbolAddress((void**)&pffo,  g_ffo);
    cudaGetSymbolAddress((void**)&peft,  g_eft);
    cudaGetSymbolAddress((void**)&pxh,   g_xh);
    cudaGetSymbolAddress((void**)&pxl,   g_xl);
    cudaGetSymbolAddress((void**)&pah,   g_ah);
    cudaGetSymbolAddress((void**)&pal,   g_al);
    cudaGetSymbolAddress((void**)&px1h,  g_x1h);
    cudaGetSymbolAddress((void**)&px1l,  g_x1l);
    cudaGetSymbolAddress((void**)&phh,   g_hh);
    cudaGetSymbolAddress((void**)&phl,   g_hl);
    cudaGetSymbolAddress((void**)&phidh, g_hidh);
    cudaGetSymbolAddress((void**)&phidl, g_hidl);
    cudaGetSymbolAddress((void**)&piwh,  g_iwh);
    cudaGetSymbolAddress((void**)&piwl,  g_iwl);
    cudaGetSymbolAddress((void**)&powh,  g_owh);
    cudaGetSymbolAddress((void**)&powl,  g_owl);
    cudaGetSymbolAddress((void**)&pw1h,  g_w1h);
    cudaGetSymbolAddress((void**)&pw1l,  g_w1l);
    cudaGetSymbolAddress((void**)&pw2h,  g_w2h);
    cudaGetSymbolAddress((void**)&pw2l,  g_w2l);
    cudaGetSymbolAddress((void**)&prwh,  g_rwh);
    cudaGetSymbolAddress((void**)&prwl,  g_rwl);

    // L0: split all weights into bf16 hi/lo planes (one launch)
    wsplit_all<<<(WN4 + 255) / 256, 256>>>(in_w, out_w, w1, w2, rnn_w);

    // L1: zero accumulators
    zero_kernel<<<(NN * NH * ND + 255) / 256, 256>>>();

    // L2: gather features
    gather_kernel<<<NELT * 32 / 256, 256>>>(features, emi);

    // L3: QKV = x @ in_w^T + in_b : [196608,128]x[384,128]
    hgemm<<<dim3(NELT / 128, 3), 256, HG_SMEM>>>(
        pxh, pxl, ND, piwh, piwl, ND, in_b, pqkv, nullptr, nullptr, 384, ND, 0);

    // L4: attention -> planes
    attn_kernel<<<NE / 8, 256>>>();

    // L5: out projection -> g_ffo fp32   (this is ncu's -s 5 target)
    hgemm<<<dim3(NELT / 128, 1), 256, HG_SMEM>>>(
        pah, pal, ND, powh, powl, ND, out_b, pffo, nullptr, nullptr, ND, ND, 0);

    // L6: x1 = LN1(x + oproj)
    addln_kernel<<<NELT / 8, 256>>>(ln1_g, ln1_b);

    // L7: FFN in 4 hidden N-chunks of FFC=512; FFN2 accumulates into g_ffo
    for (int c = 0; c < NFF / FFC; c++) {
        // FFN1 chunk: h = relu(x1 @ w1[512c:512c+512]^T + b1[512c:]) -> planes
        hgemm<<<dim3(NELT / 128, FFC / 128), 256, HG_SMEM>>>(
            px1h, px1l, ND,
            pw1h + (size_t)c * FFC * ND, pw1l + (size_t)c * FFC * ND, ND,
            b1 + c * FFC, nullptr, phh, phl, FFC, ND, 1);
        // FFN2 chunk: ffo (+)= h @ w2[:, 512c:512c+512]^T (+ b2 on first chunk)
        hgemm<<<dim3(NELT / 128, 1), 256, HG_SMEM>>>(
            phh, phl, FFC,
            pw2h + (size_t)c * FFC, pw2l + (size_t)c * FFC, NFF,
            b2, pffo, nullptr, nullptr, ND, FFC, c == 0 ? 0 : 2);
    }

    // L8: x2 = LN2(x1 + ff); hidden = mean_L(x2) -> planes
    ln2hidden_kernel<<<NE / 8, 256>>>(ln2_g, ln2_b);

    // L9: eft = hidden @ rnn_w^T + rnn_b : [65536,128]x[1024,128]
    hgemm<<<dim3(NE / 128, (NH * ND) / 128), 256, HG_SMEM>>>(
        phidh, phidl, ND, prwh, prwl, ND, rnn_b, peft, nullptr, nullptr,
        NH * ND, ND, 0);

    // L10-13: segment softmax aggregation + output gather
    amax_kernel<<<NE / 8, 256>>>(features, emi, dst, a1w, a2);
    exps_kernel<<<NE * NH / 256, 256>>>(dst);
    ftacc_kernel<<<(int)((size_t)NE * NH * ND / 256), 256>>>(dst);
    outg_kernel<<<(int)((size_t)NT * NH * ND / 256), 256>>>(tgt, out);
}